// round 8
// baseline (speedup 1.0000x reference)
#include <cuda_runtime.h>
#include <math.h>

// Precomputed row-invariant pooled-noise term: (noise[2j]+noise[2j+1])*STD/2.
// 200 KB -> L2-resident across all 512 row-CTAs.
#define MAX_POOL 65536
__device__ float g_npool[MAX_POOL];

__global__ void npool_kernel(const float* __restrict__ noise, int halfL) {
    int j = blockIdx.x * blockDim.x + threadIdx.x;
    if (j < halfL)
        g_npool[j] = (noise[2 * j] + noise[2 * j + 1]) * 0.02f;  // STD=0.04, /2
}

// One CTA per row; pooled row staged in SMEM; single DRAM pass each way.
// 512 threads -> 128-reg budget so ptxas can front-batch the LDG.128s (MLP).
__global__ __launch_bounds__(512, 1)
void fused_kernel(const float* __restrict__ x,
                  const int*   __restrict__ move_p,
                  float*       __restrict__ out,
                  int L) {
    extern __shared__ float s_pool[];          // halfL floats + 40 reduction slots
    const int halfL = L >> 1;
    float* s_red = s_pool + halfL;

    const int row = blockIdx.x;
    const float* __restrict__ xrow = x + (size_t)row * (size_t)L;
    float*       __restrict__ orow = out + (size_t)row * (size_t)L;

    int mv = __ldg(move_p);
    mv %= L; if (mv < 0) mv += L;

    const int ngroups = halfL >> 2;            // groups of 4 pooled values
    const int tid = threadIdx.x, bs = blockDim.x;

    // Fast-path group interval [glo, ghi): s0 = 8g - mv needs s0>=0, s0+7<L,
    // and 16B alignment (mv % 4 == 0).
    int glo, ghi;
    if ((mv & 3) == 0) {
        glo = (mv + 7) >> 3;
        if (glo > ngroups) glo = ngroups;
        ghi = (L + mv - 8) / 8 + 1;
        if (ghi > ngroups) ghi = ngroups;
        if (ghi < glo)     ghi = glo;
    } else {
        glo = 0; ghi = 0;                      // everything via scalar path
    }

    float sum = 0.0f, sumsq = 0.0f;

    // ---- scalar edges (wrap region; ~13 groups for small mv) ----
    for (int e = tid; e < glo + (ngroups - ghi); e += bs) {
        int g = (e < glo) ? e : (ghi + (e - glo));
        int j0 = g << 2;
        #pragma unroll
        for (int k = 0; k < 4; k++) {
            int j = j0 + k;
            int s = 2 * j - mv;
            if (s < 0) s += L; else if (s >= L) s -= L;
            int s1 = s + 1; if (s1 >= L) s1 -= L;
            float p = (xrow[s] + xrow[s1]) * 0.5f + g_npool[j];
            s_pool[j] = p;
            sum += p; sumsq = fmaf(p, p, sumsq);
        }
    }
    // tail j (halfL % 4 != 0)
    for (int j = (ngroups << 2) + tid; j < halfL; j += bs) {
        int s = 2 * j - mv;
        if (s < 0) s += L; else if (s >= L) s -= L;
        int s1 = s + 1; if (s1 >= L) s1 -= L;
        float p = (xrow[s] + xrow[s1]) * 0.5f + g_npool[j];
        s_pool[j] = p;
        sum += p; sumsq = fmaf(p, p, sumsq);
    }

    // ---- hot loop: 2 groups / iter, all 6 LDG.128s issued before any use ----
    int g = glo + tid;
    #pragma unroll 2
    for (; g + bs < ghi; g += 2 * bs) {
        const int gA = g, gB = g + bs;
        const int jA = gA << 2, jB = gB << 2;
        const int sA = (gA << 3) - mv, sB = (gB << 3) - mv;
        // batched loads (independent; fills the LSU pipeline)
        float4 a0 = __ldcs(reinterpret_cast<const float4*>(xrow + sA));
        float4 a1 = __ldcs(reinterpret_cast<const float4*>(xrow + sA + 4));
        float4 b0 = __ldcs(reinterpret_cast<const float4*>(xrow + sB));
        float4 b1 = __ldcs(reinterpret_cast<const float4*>(xrow + sB + 4));
        float4 nA = *reinterpret_cast<const float4*>(g_npool + jA);
        float4 nB = *reinterpret_cast<const float4*>(g_npool + jB);

        float4 pA, pB;
        pA.x = (a0.x + a0.y) * 0.5f + nA.x;
        pA.y = (a0.z + a0.w) * 0.5f + nA.y;
        pA.z = (a1.x + a1.y) * 0.5f + nA.z;
        pA.w = (a1.z + a1.w) * 0.5f + nA.w;
        pB.x = (b0.x + b0.y) * 0.5f + nB.x;
        pB.y = (b0.z + b0.w) * 0.5f + nB.y;
        pB.z = (b1.x + b1.y) * 0.5f + nB.z;
        pB.w = (b1.z + b1.w) * 0.5f + nB.w;

        *reinterpret_cast<float4*>(s_pool + jA) = pA;
        *reinterpret_cast<float4*>(s_pool + jB) = pB;

        sum  += (pA.x + pA.y) + (pA.z + pA.w) + (pB.x + pB.y) + (pB.z + pB.w);
        sumsq = fmaf(pA.x, pA.x, sumsq); sumsq = fmaf(pA.y, pA.y, sumsq);
        sumsq = fmaf(pA.z, pA.z, sumsq); sumsq = fmaf(pA.w, pA.w, sumsq);
        sumsq = fmaf(pB.x, pB.x, sumsq); sumsq = fmaf(pB.y, pB.y, sumsq);
        sumsq = fmaf(pB.z, pB.z, sumsq); sumsq = fmaf(pB.w, pB.w, sumsq);
    }
    for (; g < ghi; g += bs) {                 // remainder (<= 1 group/thread)
        const int j0 = g << 2;
        const int s0 = (g << 3) - mv;
        float4 a  = __ldcs(reinterpret_cast<const float4*>(xrow + s0));
        float4 b  = __ldcs(reinterpret_cast<const float4*>(xrow + s0 + 4));
        float4 np = *reinterpret_cast<const float4*>(g_npool + j0);
        float4 pv;
        pv.x = (a.x + a.y) * 0.5f + np.x;
        pv.y = (a.z + a.w) * 0.5f + np.y;
        pv.z = (b.x + b.y) * 0.5f + np.z;
        pv.w = (b.z + b.w) * 0.5f + np.w;
        *reinterpret_cast<float4*>(s_pool + j0) = pv;
        sum  += (pv.x + pv.y) + (pv.z + pv.w);
        sumsq = fmaf(pv.x, pv.x, sumsq); sumsq = fmaf(pv.y, pv.y, sumsq);
        sumsq = fmaf(pv.z, pv.z, sumsq); sumsq = fmaf(pv.w, pv.w, sumsq);
    }

    // ---- block reduction of (sum, sumsq) ----
    #pragma unroll
    for (int o = 16; o > 0; o >>= 1) {
        sum   += __shfl_down_sync(0xFFFFFFFFu, sum,   o);
        sumsq += __shfl_down_sync(0xFFFFFFFFu, sumsq, o);
    }
    const int wid  = tid >> 5;
    const int lane = tid & 31;
    const int nwarps = bs >> 5;
    if (lane == 0) { s_red[wid] = sum; s_red[16 + wid] = sumsq; }
    __syncthreads();
    if (tid < 32) {
        float s2 = (tid < nwarps) ? s_red[tid]      : 0.0f;
        float q2 = (tid < nwarps) ? s_red[16 + tid] : 0.0f;
        #pragma unroll
        for (int o = 8; o > 0; o >>= 1) {
            s2 += __shfl_down_sync(0xFFFFFFFFu, s2, o);
            q2 += __shfl_down_sync(0xFFFFFFFFu, q2, o);
        }
        if (tid == 0) {
            float inv_n = 1.0f / (float)halfL;
            float mu    = s2 * inv_n;
            float var   = fmaxf(q2 * inv_n - mu * mu, 0.0f);
            s_red[32] = mu;
            s_red[33] = rsqrtf(var);
        }
    }
    __syncthreads();
    const float mu     = s_red[32];
    const float inv_sd = s_red[33];

    // ---- Phase B: 2 groups / iter, LDS.128 + 2x streaming STG.128 each ----
    int h = tid;
    #pragma unroll 2
    for (; h + bs < ngroups; h += 2 * bs) {
        const int jA = h << 2, jB = (h + bs) << 2;
        float4 pA = *reinterpret_cast<const float4*>(s_pool + jA);
        float4 pB = *reinterpret_cast<const float4*>(s_pool + jB);
        float vA0 = (pA.x - mu) * inv_sd, vA1 = (pA.y - mu) * inv_sd;
        float vA2 = (pA.z - mu) * inv_sd, vA3 = (pA.w - mu) * inv_sd;
        float vB0 = (pB.x - mu) * inv_sd, vB1 = (pB.y - mu) * inv_sd;
        float vB2 = (pB.z - mu) * inv_sd, vB3 = (pB.w - mu) * inv_sd;
        float4 wA0 = {vA0, vA0, vA1, vA1}, wA1 = {vA2, vA2, vA3, vA3};
        float4 wB0 = {vB0, vB0, vB1, vB1}, wB1 = {vB2, vB2, vB3, vB3};
        __stcs(reinterpret_cast<float4*>(orow + (jA << 1)),     wA0);
        __stcs(reinterpret_cast<float4*>(orow + (jA << 1) + 4), wA1);
        __stcs(reinterpret_cast<float4*>(orow + (jB << 1)),     wB0);
        __stcs(reinterpret_cast<float4*>(orow + (jB << 1) + 4), wB1);
    }
    for (; h < ngroups; h += bs) {
        const int j0 = h << 2;
        float4 p = *reinterpret_cast<const float4*>(s_pool + j0);
        float v0 = (p.x - mu) * inv_sd, v1 = (p.y - mu) * inv_sd;
        float v2 = (p.z - mu) * inv_sd, v3 = (p.w - mu) * inv_sd;
        float4 w0 = {v0, v0, v1, v1}, w1 = {v2, v2, v3, v3};
        __stcs(reinterpret_cast<float4*>(orow + (j0 << 1)),     w0);
        __stcs(reinterpret_cast<float4*>(orow + (j0 << 1) + 4), w1);
    }
    for (int j = (ngroups << 2) + tid; j < halfL; j += bs) {
        float v = (s_pool[j] - mu) * inv_sd;
        orow[2 * j]     = v;
        orow[2 * j + 1] = v;
    }
}

extern "C" void kernel_launch(void* const* d_in, const int* in_sizes, int n_in,
                              void* d_out, int out_size) {
    const float* x     = (const float*)d_in[0];
    const float* noise = (const float*)d_in[1];
    const int*   move  = (const int*)d_in[2];
    float*       out   = (float*)d_out;

    const int L = in_sizes[1];               // 100000
    const int B = in_sizes[0] / L;           // 512
    const int halfL = L / 2;

    npool_kernel<<<(halfL + 255) / 256, 256>>>(noise, halfL);

    size_t smem = (size_t)halfL * sizeof(float) + 40 * sizeof(float);
    cudaFuncSetAttribute(fused_kernel,
                         cudaFuncAttributeMaxDynamicSharedMemorySize,
                         (int)smem);
    fused_kernel<<<B, 512, smem>>>(x, move, out, L);
}

// round 9
// speedup vs baseline: 1.0076x; 1.0076x over previous
#include <cuda_runtime.h>
#include <math.h>

// Precomputed row-invariant pooled-noise term: (noise[2j]+noise[2j+1])*STD/2.
// 200 KB -> L2-resident across all 512 row-CTAs.
#define MAX_POOL 65536
__device__ float g_npool[MAX_POOL];

__global__ void npool_kernel(const float* __restrict__ noise, int halfL) {
    int j = blockIdx.x * blockDim.x + threadIdx.x;
    if (j < halfL)
        g_npool[j] = (noise[2 * j] + noise[2 * j + 1]) * 0.02f;  // STD=0.04, /2
}

// One CTA per row; pooled row staged in SMEM; single DRAM pass each way.
// 512 threads -> 128-reg budget so ptxas can front-batch the LDG.128s (MLP).
__global__ __launch_bounds__(512, 1)
void fused_kernel(const float* __restrict__ x,
                  const int*   __restrict__ move_p,
                  float*       __restrict__ out,
                  int L) {
    extern __shared__ float s_pool[];          // halfL floats + 40 reduction slots
    const int halfL = L >> 1;
    float* s_red = s_pool + halfL;

    const int row = blockIdx.x;
    const float* __restrict__ xrow = x + (size_t)row * (size_t)L;
    float*       __restrict__ orow = out + (size_t)row * (size_t)L;

    int mv = __ldg(move_p);
    mv %= L; if (mv < 0) mv += L;

    const int ngroups = halfL >> 2;            // groups of 4 pooled values
    const int tid = threadIdx.x, bs = blockDim.x;

    // Fast-path group interval [glo, ghi): s0 = 8g - mv needs s0>=0, s0+7<L,
    // and 16B alignment (mv % 4 == 0).
    int glo, ghi;
    if ((mv & 3) == 0) {
        glo = (mv + 7) >> 3;
        if (glo > ngroups) glo = ngroups;
        ghi = (L + mv - 8) / 8 + 1;
        if (ghi > ngroups) ghi = ngroups;
        if (ghi < glo)     ghi = glo;
    } else {
        glo = 0; ghi = 0;                      // everything via scalar path
    }

    float sum = 0.0f, sumsq = 0.0f;

    // ---- scalar edges (wrap region; ~13 groups for small mv) ----
    for (int e = tid; e < glo + (ngroups - ghi); e += bs) {
        int g = (e < glo) ? e : (ghi + (e - glo));
        int j0 = g << 2;
        #pragma unroll
        for (int k = 0; k < 4; k++) {
            int j = j0 + k;
            int s = 2 * j - mv;
            if (s < 0) s += L; else if (s >= L) s -= L;
            int s1 = s + 1; if (s1 >= L) s1 -= L;
            float p = (xrow[s] + xrow[s1]) * 0.5f + g_npool[j];
            s_pool[j] = p;
            sum += p; sumsq = fmaf(p, p, sumsq);
        }
    }
    // tail j (halfL % 4 != 0)
    for (int j = (ngroups << 2) + tid; j < halfL; j += bs) {
        int s = 2 * j - mv;
        if (s < 0) s += L; else if (s >= L) s -= L;
        int s1 = s + 1; if (s1 >= L) s1 -= L;
        float p = (xrow[s] + xrow[s1]) * 0.5f + g_npool[j];
        s_pool[j] = p;
        sum += p; sumsq = fmaf(p, p, sumsq);
    }

    // ---- hot loop: 2 groups / iter, all 6 LDG.128s issued before any use ----
    int g = glo + tid;
    #pragma unroll 2
    for (; g + bs < ghi; g += 2 * bs) {
        const int gA = g, gB = g + bs;
        const int jA = gA << 2, jB = gB << 2;
        const int sA = (gA << 3) - mv, sB = (gB << 3) - mv;
        // batched loads (independent; fills the LSU pipeline)
        float4 a0 = __ldcs(reinterpret_cast<const float4*>(xrow + sA));
        float4 a1 = __ldcs(reinterpret_cast<const float4*>(xrow + sA + 4));
        float4 b0 = __ldcs(reinterpret_cast<const float4*>(xrow + sB));
        float4 b1 = __ldcs(reinterpret_cast<const float4*>(xrow + sB + 4));
        float4 nA = *reinterpret_cast<const float4*>(g_npool + jA);
        float4 nB = *reinterpret_cast<const float4*>(g_npool + jB);

        float4 pA, pB;
        pA.x = (a0.x + a0.y) * 0.5f + nA.x;
        pA.y = (a0.z + a0.w) * 0.5f + nA.y;
        pA.z = (a1.x + a1.y) * 0.5f + nA.z;
        pA.w = (a1.z + a1.w) * 0.5f + nA.w;
        pB.x = (b0.x + b0.y) * 0.5f + nB.x;
        pB.y = (b0.z + b0.w) * 0.5f + nB.y;
        pB.z = (b1.x + b1.y) * 0.5f + nB.z;
        pB.w = (b1.z + b1.w) * 0.5f + nB.w;

        *reinterpret_cast<float4*>(s_pool + jA) = pA;
        *reinterpret_cast<float4*>(s_pool + jB) = pB;

        sum  += (pA.x + pA.y) + (pA.z + pA.w) + (pB.x + pB.y) + (pB.z + pB.w);
        sumsq = fmaf(pA.x, pA.x, sumsq); sumsq = fmaf(pA.y, pA.y, sumsq);
        sumsq = fmaf(pA.z, pA.z, sumsq); sumsq = fmaf(pA.w, pA.w, sumsq);
        sumsq = fmaf(pB.x, pB.x, sumsq); sumsq = fmaf(pB.y, pB.y, sumsq);
        sumsq = fmaf(pB.z, pB.z, sumsq); sumsq = fmaf(pB.w, pB.w, sumsq);
    }
    for (; g < ghi; g += bs) {                 // remainder (<= 1 group/thread)
        const int j0 = g << 2;
        const int s0 = (g << 3) - mv;
        float4 a  = __ldcs(reinterpret_cast<const float4*>(xrow + s0));
        float4 b  = __ldcs(reinterpret_cast<const float4*>(xrow + s0 + 4));
        float4 np = *reinterpret_cast<const float4*>(g_npool + j0);
        float4 pv;
        pv.x = (a.x + a.y) * 0.5f + np.x;
        pv.y = (a.z + a.w) * 0.5f + np.y;
        pv.z = (b.x + b.y) * 0.5f + np.z;
        pv.w = (b.z + b.w) * 0.5f + np.w;
        *reinterpret_cast<float4*>(s_pool + j0) = pv;
        sum  += (pv.x + pv.y) + (pv.z + pv.w);
        sumsq = fmaf(pv.x, pv.x, sumsq); sumsq = fmaf(pv.y, pv.y, sumsq);
        sumsq = fmaf(pv.z, pv.z, sumsq); sumsq = fmaf(pv.w, pv.w, sumsq);
    }

    // ---- block reduction of (sum, sumsq) ----
    #pragma unroll
    for (int o = 16; o > 0; o >>= 1) {
        sum   += __shfl_down_sync(0xFFFFFFFFu, sum,   o);
        sumsq += __shfl_down_sync(0xFFFFFFFFu, sumsq, o);
    }
    const int wid  = tid >> 5;
    const int lane = tid & 31;
    const int nwarps = bs >> 5;
    if (lane == 0) { s_red[wid] = sum; s_red[16 + wid] = sumsq; }
    __syncthreads();
    if (tid < 32) {
        float s2 = (tid < nwarps) ? s_red[tid]      : 0.0f;
        float q2 = (tid < nwarps) ? s_red[16 + tid] : 0.0f;
        #pragma unroll
        for (int o = 8; o > 0; o >>= 1) {
            s2 += __shfl_down_sync(0xFFFFFFFFu, s2, o);
            q2 += __shfl_down_sync(0xFFFFFFFFu, q2, o);
        }
        if (tid == 0) {
            float inv_n = 1.0f / (float)halfL;
            float mu    = s2 * inv_n;
            float var   = fmaxf(q2 * inv_n - mu * mu, 0.0f);
            s_red[32] = mu;
            s_red[33] = rsqrtf(var);
        }
    }
    __syncthreads();
    const float mu     = s_red[32];
    const float inv_sd = s_red[33];

    // ---- Phase B: 2 groups / iter, LDS.128 + 2x streaming STG.128 each ----
    int h = tid;
    #pragma unroll 2
    for (; h + bs < ngroups; h += 2 * bs) {
        const int jA = h << 2, jB = (h + bs) << 2;
        float4 pA = *reinterpret_cast<const float4*>(s_pool + jA);
        float4 pB = *reinterpret_cast<const float4*>(s_pool + jB);
        float vA0 = (pA.x - mu) * inv_sd, vA1 = (pA.y - mu) * inv_sd;
        float vA2 = (pA.z - mu) * inv_sd, vA3 = (pA.w - mu) * inv_sd;
        float vB0 = (pB.x - mu) * inv_sd, vB1 = (pB.y - mu) * inv_sd;
        float vB2 = (pB.z - mu) * inv_sd, vB3 = (pB.w - mu) * inv_sd;
        float4 wA0 = {vA0, vA0, vA1, vA1}, wA1 = {vA2, vA2, vA3, vA3};
        float4 wB0 = {vB0, vB0, vB1, vB1}, wB1 = {vB2, vB2, vB3, vB3};
        __stcs(reinterpret_cast<float4*>(orow + (jA << 1)),     wA0);
        __stcs(reinterpret_cast<float4*>(orow + (jA << 1) + 4), wA1);
        __stcs(reinterpret_cast<float4*>(orow + (jB << 1)),     wB0);
        __stcs(reinterpret_cast<float4*>(orow + (jB << 1) + 4), wB1);
    }
    for (; h < ngroups; h += bs) {
        const int j0 = h << 2;
        float4 p = *reinterpret_cast<const float4*>(s_pool + j0);
        float v0 = (p.x - mu) * inv_sd, v1 = (p.y - mu) * inv_sd;
        float v2 = (p.z - mu) * inv_sd, v3 = (p.w - mu) * inv_sd;
        float4 w0 = {v0, v0, v1, v1}, w1 = {v2, v2, v3, v3};
        __stcs(reinterpret_cast<float4*>(orow + (j0 << 1)),     w0);
        __stcs(reinterpret_cast<float4*>(orow + (j0 << 1) + 4), w1);
    }
    for (int j = (ngroups << 2) + tid; j < halfL; j += bs) {
        float v = (s_pool[j] - mu) * inv_sd;
        orow[2 * j]     = v;
        orow[2 * j + 1] = v;
    }
}

extern "C" void kernel_launch(void* const* d_in, const int* in_sizes, int n_in,
                              void* d_out, int out_size) {
    const float* x     = (const float*)d_in[0];
    const float* noise = (const float*)d_in[1];
    const int*   move  = (const int*)d_in[2];
    float*       out   = (float*)d_out;

    const int L = in_sizes[1];               // 100000
    const int B = in_sizes[0] / L;           // 512
    const int halfL = L / 2;

    npool_kernel<<<(halfL + 255) / 256, 256>>>(noise, halfL);

    size_t smem = (size_t)halfL * sizeof(float) + 40 * sizeof(float);
    cudaFuncSetAttribute(fused_kernel,
                         cudaFuncAttributeMaxDynamicSharedMemorySize,
                         (int)smem);
    fused_kernel<<<B, 512, smem>>>(x, move, out, L);
}

// round 10
// speedup vs baseline: 1.0079x; 1.0002x over previous
#include <cuda_runtime.h>
#include <math.h>

// Precomputed row-invariant pooled-noise term: (noise[2j]+noise[2j+1])*STD/2.
// 200 KB -> L2-resident across all 512 row-CTAs.
#define MAX_POOL 65536
__device__ float g_npool[MAX_POOL];

__global__ void npool_kernel(const float* __restrict__ noise, int halfL) {
    int j = blockIdx.x * blockDim.x + threadIdx.x;
    if (j < halfL)
        g_npool[j] = (noise[2 * j] + noise[2 * j + 1]) * 0.02f;  // STD=0.04, /2
}

// One CTA per row; pooled row staged in SMEM; single DRAM pass each way.
// 512 threads -> 128-reg budget so ptxas can front-batch the LDG.128s (MLP).
__global__ __launch_bounds__(512, 1)
void fused_kernel(const float* __restrict__ x,
                  const int*   __restrict__ move_p,
                  float*       __restrict__ out,
                  int L) {
    extern __shared__ float s_pool[];          // halfL floats + 40 reduction slots
    const int halfL = L >> 1;
    float* s_red = s_pool + halfL;

    const int row = blockIdx.x;
    const float* __restrict__ xrow = x + (size_t)row * (size_t)L;
    float*       __restrict__ orow = out + (size_t)row * (size_t)L;

    int mv = __ldg(move_p);
    mv %= L; if (mv < 0) mv += L;

    const int ngroups = halfL >> 2;            // groups of 4 pooled values
    const int tid = threadIdx.x, bs = blockDim.x;

    // Fast-path group interval [glo, ghi): s0 = 8g - mv needs s0>=0, s0+7<L,
    // and 16B alignment (mv % 4 == 0).
    int glo, ghi;
    if ((mv & 3) == 0) {
        glo = (mv + 7) >> 3;
        if (glo > ngroups) glo = ngroups;
        ghi = (L + mv - 8) / 8 + 1;
        if (ghi > ngroups) ghi = ngroups;
        if (ghi < glo)     ghi = glo;
    } else {
        glo = 0; ghi = 0;                      // everything via scalar path
    }

    float sum = 0.0f, sumsq = 0.0f;

    // ---- scalar edges (wrap region; ~13 groups for small mv) ----
    for (int e = tid; e < glo + (ngroups - ghi); e += bs) {
        int g = (e < glo) ? e : (ghi + (e - glo));
        int j0 = g << 2;
        #pragma unroll
        for (int k = 0; k < 4; k++) {
            int j = j0 + k;
            int s = 2 * j - mv;
            if (s < 0) s += L; else if (s >= L) s -= L;
            int s1 = s + 1; if (s1 >= L) s1 -= L;
            float p = (xrow[s] + xrow[s1]) * 0.5f + g_npool[j];
            s_pool[j] = p;
            sum += p; sumsq = fmaf(p, p, sumsq);
        }
    }
    // tail j (halfL % 4 != 0)
    for (int j = (ngroups << 2) + tid; j < halfL; j += bs) {
        int s = 2 * j - mv;
        if (s < 0) s += L; else if (s >= L) s -= L;
        int s1 = s + 1; if (s1 >= L) s1 -= L;
        float p = (xrow[s] + xrow[s1]) * 0.5f + g_npool[j];
        s_pool[j] = p;
        sum += p; sumsq = fmaf(p, p, sumsq);
    }

    // ---- hot loop: 2 groups / iter, all 6 LDG.128s issued before any use ----
    int g = glo + tid;
    #pragma unroll 2
    for (; g + bs < ghi; g += 2 * bs) {
        const int gA = g, gB = g + bs;
        const int jA = gA << 2, jB = gB << 2;
        const int sA = (gA << 3) - mv, sB = (gB << 3) - mv;
        // batched loads (independent; fills the LSU pipeline)
        float4 a0 = __ldcs(reinterpret_cast<const float4*>(xrow + sA));
        float4 a1 = __ldcs(reinterpret_cast<const float4*>(xrow + sA + 4));
        float4 b0 = __ldcs(reinterpret_cast<const float4*>(xrow + sB));
        float4 b1 = __ldcs(reinterpret_cast<const float4*>(xrow + sB + 4));
        float4 nA = *reinterpret_cast<const float4*>(g_npool + jA);
        float4 nB = *reinterpret_cast<const float4*>(g_npool + jB);

        float4 pA, pB;
        pA.x = (a0.x + a0.y) * 0.5f + nA.x;
        pA.y = (a0.z + a0.w) * 0.5f + nA.y;
        pA.z = (a1.x + a1.y) * 0.5f + nA.z;
        pA.w = (a1.z + a1.w) * 0.5f + nA.w;
        pB.x = (b0.x + b0.y) * 0.5f + nB.x;
        pB.y = (b0.z + b0.w) * 0.5f + nB.y;
        pB.z = (b1.x + b1.y) * 0.5f + nB.z;
        pB.w = (b1.z + b1.w) * 0.5f + nB.w;

        *reinterpret_cast<float4*>(s_pool + jA) = pA;
        *reinterpret_cast<float4*>(s_pool + jB) = pB;

        sum  += (pA.x + pA.y) + (pA.z + pA.w) + (pB.x + pB.y) + (pB.z + pB.w);
        sumsq = fmaf(pA.x, pA.x, sumsq); sumsq = fmaf(pA.y, pA.y, sumsq);
        sumsq = fmaf(pA.z, pA.z, sumsq); sumsq = fmaf(pA.w, pA.w, sumsq);
        sumsq = fmaf(pB.x, pB.x, sumsq); sumsq = fmaf(pB.y, pB.y, sumsq);
        sumsq = fmaf(pB.z, pB.z, sumsq); sumsq = fmaf(pB.w, pB.w, sumsq);
    }
    for (; g < ghi; g += bs) {                 // remainder (<= 1 group/thread)
        const int j0 = g << 2;
        const int s0 = (g << 3) - mv;
        float4 a  = __ldcs(reinterpret_cast<const float4*>(xrow + s0));
        float4 b  = __ldcs(reinterpret_cast<const float4*>(xrow + s0 + 4));
        float4 np = *reinterpret_cast<const float4*>(g_npool + j0);
        float4 pv;
        pv.x = (a.x + a.y) * 0.5f + np.x;
        pv.y = (a.z + a.w) * 0.5f + np.y;
        pv.z = (b.x + b.y) * 0.5f + np.z;
        pv.w = (b.z + b.w) * 0.5f + np.w;
        *reinterpret_cast<float4*>(s_pool + j0) = pv;
        sum  += (pv.x + pv.y) + (pv.z + pv.w);
        sumsq = fmaf(pv.x, pv.x, sumsq); sumsq = fmaf(pv.y, pv.y, sumsq);
        sumsq = fmaf(pv.z, pv.z, sumsq); sumsq = fmaf(pv.w, pv.w, sumsq);
    }

    // ---- block reduction of (sum, sumsq) ----
    #pragma unroll
    for (int o = 16; o > 0; o >>= 1) {
        sum   += __shfl_down_sync(0xFFFFFFFFu, sum,   o);
        sumsq += __shfl_down_sync(0xFFFFFFFFu, sumsq, o);
    }
    const int wid  = tid >> 5;
    const int lane = tid & 31;
    const int nwarps = bs >> 5;
    if (lane == 0) { s_red[wid] = sum; s_red[16 + wid] = sumsq; }
    __syncthreads();
    if (tid < 32) {
        float s2 = (tid < nwarps) ? s_red[tid]      : 0.0f;
        float q2 = (tid < nwarps) ? s_red[16 + tid] : 0.0f;
        #pragma unroll
        for (int o = 8; o > 0; o >>= 1) {
            s2 += __shfl_down_sync(0xFFFFFFFFu, s2, o);
            q2 += __shfl_down_sync(0xFFFFFFFFu, q2, o);
        }
        if (tid == 0) {
            float inv_n = 1.0f / (float)halfL;
            float mu    = s2 * inv_n;
            float var   = fmaxf(q2 * inv_n - mu * mu, 0.0f);
            s_red[32] = mu;
            s_red[33] = rsqrtf(var);
        }
    }
    __syncthreads();
    const float mu     = s_red[32];
    const float inv_sd = s_red[33];

    // ---- Phase B: 2 groups / iter, LDS.128 + 2x streaming STG.128 each ----
    int h = tid;
    #pragma unroll 2
    for (; h + bs < ngroups; h += 2 * bs) {
        const int jA = h << 2, jB = (h + bs) << 2;
        float4 pA = *reinterpret_cast<const float4*>(s_pool + jA);
        float4 pB = *reinterpret_cast<const float4*>(s_pool + jB);
        float vA0 = (pA.x - mu) * inv_sd, vA1 = (pA.y - mu) * inv_sd;
        float vA2 = (pA.z - mu) * inv_sd, vA3 = (pA.w - mu) * inv_sd;
        float vB0 = (pB.x - mu) * inv_sd, vB1 = (pB.y - mu) * inv_sd;
        float vB2 = (pB.z - mu) * inv_sd, vB3 = (pB.w - mu) * inv_sd;
        float4 wA0 = {vA0, vA0, vA1, vA1}, wA1 = {vA2, vA2, vA3, vA3};
        float4 wB0 = {vB0, vB0, vB1, vB1}, wB1 = {vB2, vB2, vB3, vB3};
        __stcs(reinterpret_cast<float4*>(orow + (jA << 1)),     wA0);
        __stcs(reinterpret_cast<float4*>(orow + (jA << 1) + 4), wA1);
        __stcs(reinterpret_cast<float4*>(orow + (jB << 1)),     wB0);
        __stcs(reinterpret_cast<float4*>(orow + (jB << 1) + 4), wB1);
    }
    for (; h < ngroups; h += bs) {
        const int j0 = h << 2;
        float4 p = *reinterpret_cast<const float4*>(s_pool + j0);
        float v0 = (p.x - mu) * inv_sd, v1 = (p.y - mu) * inv_sd;
        float v2 = (p.z - mu) * inv_sd, v3 = (p.w - mu) * inv_sd;
        float4 w0 = {v0, v0, v1, v1}, w1 = {v2, v2, v3, v3};
        __stcs(reinterpret_cast<float4*>(orow + (j0 << 1)),     w0);
        __stcs(reinterpret_cast<float4*>(orow + (j0 << 1) + 4), w1);
    }
    for (int j = (ngroups << 2) + tid; j < halfL; j += bs) {
        float v = (s_pool[j] - mu) * inv_sd;
        orow[2 * j]     = v;
        orow[2 * j + 1] = v;
    }
}

extern "C" void kernel_launch(void* const* d_in, const int* in_sizes, int n_in,
                              void* d_out, int out_size) {
    const float* x     = (const float*)d_in[0];
    const float* noise = (const float*)d_in[1];
    const int*   move  = (const int*)d_in[2];
    float*       out   = (float*)d_out;

    const int L = in_sizes[1];               // 100000
    const int B = in_sizes[0] / L;           // 512
    const int halfL = L / 2;

    npool_kernel<<<(halfL + 255) / 256, 256>>>(noise, halfL);

    size_t smem = (size_t)halfL * sizeof(float) + 40 * sizeof(float);
    cudaFuncSetAttribute(fused_kernel,
                         cudaFuncAttributeMaxDynamicSharedMemorySize,
                         (int)smem);
    fused_kernel<<<B, 512, smem>>>(x, move, out, L);
}

// round 11
// speedup vs baseline: 1.0936x; 1.0851x over previous
#include <cuda_runtime.h>
#include <math.h>

#define MAX_B    512
#define MAX_HALF 50048
#define CPR      16          // chunk CTAs per row
#define NT       256         // threads per CTA

// Row-invariant pooled noise: (noise[2j]+noise[2j+1])*STD/2 (STD=0.04)
__device__ float  g_npool[MAX_HALF];
// Pooled rows scratch (102 MB) — written pass1, read pass2, L2-biased.
__device__ float  g_pool[(size_t)MAX_B * MAX_HALF];
// Per-(row,chunk) partial moments {sum, sumsq}
__device__ float2 g_part[MAX_B * CPR];

__global__ void npool_kernel(const float* __restrict__ noise, int halfL) {
    int j = blockIdx.x * blockDim.x + threadIdx.x;
    if (j < halfL)
        g_npool[j] = (noise[2 * j] + noise[2 * j + 1]) * 0.02f;
}

// Pass 1: stream x, compute pooled values into g_pool, partial moments to g_part.
__global__ __launch_bounds__(NT)
void pass1_kernel(const float* __restrict__ x,
                  const int*   __restrict__ move_p,
                  int L) {
    const int halfL   = L >> 1;
    const int ngroups = halfL >> 2;                 // float4 groups of pooled
    const int gpc     = (ngroups + CPR - 1) / CPR;  // groups per chunk
    const int row     = blockIdx.x / CPR;
    const int c       = blockIdx.x % CPR;
    const int gc_lo   = c * gpc;
    const int gc_hi   = min(gc_lo + gpc, ngroups);
    const int tid     = threadIdx.x;

    const float* __restrict__ xrow = x + (size_t)row * (size_t)L;
    float*       __restrict__ prow = g_pool + (size_t)row * (size_t)halfL;

    int mv = __ldg(move_p);
    mv %= L; if (mv < 0) mv += L;

    // Row-wide fast-path group interval [fl, fh): needs s0=8g-mv in-range & 16B aligned
    int fl, fh;
    if ((mv & 3) == 0) {
        fl = (mv + 7) >> 3;            if (fl > ngroups) fl = ngroups;
        fh = (L + mv - 8) / 8 + 1;     if (fh > ngroups) fh = ngroups;
        if (fh < fl) fh = fl;
    } else { fl = 0; fh = 0; }

    // Intersect with this chunk
    int lo = max(gc_lo, fl); if (lo > gc_hi) lo = gc_hi;
    int hi = min(gc_hi, fh); if (hi < lo)    hi = lo;

    float sum = 0.0f, sumsq = 0.0f;

    // ---- scalar groups in this chunk (outside fast interval) ----
    const int n_low = lo - gc_lo, n_high = gc_hi - hi;
    for (int e = tid; e < n_low + n_high; e += NT) {
        int g = (e < n_low) ? (gc_lo + e) : (hi + (e - n_low));
        int j0 = g << 2;
        #pragma unroll
        for (int k = 0; k < 4; k++) {
            int j = j0 + k;
            int s = 2 * j - mv;
            if (s < 0) s += L; else if (s >= L) s -= L;
            int s1 = s + 1; if (s1 >= L) s1 -= L;
            float p = (xrow[s] + xrow[s1]) * 0.5f + g_npool[j];
            prow[j] = p;
            sum += p; sumsq = fmaf(p, p, sumsq);
        }
    }
    // tail pooled indices (halfL % 4 != 0), owned by last chunk
    if (c == CPR - 1) {
        for (int j = (ngroups << 2) + tid; j < halfL; j += NT) {
            int s = 2 * j - mv;
            if (s < 0) s += L; else if (s >= L) s -= L;
            int s1 = s + 1; if (s1 >= L) s1 -= L;
            float p = (xrow[s] + xrow[s1]) * 0.5f + g_npool[j];
            prow[j] = p;
            sum += p; sumsq = fmaf(p, p, sumsq);
        }
    }

    // ---- fast loop: 2x LDG.128 (x, streaming) + LDG.128 (npool, L2) + STG.128 ----
    for (int g = lo + tid; g < hi; g += NT) {
        const int j0 = g << 2;
        const int s0 = (g << 3) - mv;
        float4 a  = __ldcs(reinterpret_cast<const float4*>(xrow + s0));
        float4 b  = __ldcs(reinterpret_cast<const float4*>(xrow + s0 + 4));
        float4 np = *reinterpret_cast<const float4*>(g_npool + j0);
        float4 pv;
        pv.x = (a.x + a.y) * 0.5f + np.x;
        pv.y = (a.z + a.w) * 0.5f + np.y;
        pv.z = (b.x + b.y) * 0.5f + np.z;
        pv.w = (b.z + b.w) * 0.5f + np.w;
        *reinterpret_cast<float4*>(prow + j0) = pv;   // keep in L2
        sum  += (pv.x + pv.y) + (pv.z + pv.w);
        sumsq = fmaf(pv.x, pv.x, sumsq); sumsq = fmaf(pv.y, pv.y, sumsq);
        sumsq = fmaf(pv.z, pv.z, sumsq); sumsq = fmaf(pv.w, pv.w, sumsq);
    }

    // ---- deterministic block reduction ----
    __shared__ float s_s[NT / 32], s_q[NT / 32];
    #pragma unroll
    for (int o = 16; o > 0; o >>= 1) {
        sum   += __shfl_down_sync(0xFFFFFFFFu, sum,   o);
        sumsq += __shfl_down_sync(0xFFFFFFFFu, sumsq, o);
    }
    if ((tid & 31) == 0) { s_s[tid >> 5] = sum; s_q[tid >> 5] = sumsq; }
    __syncthreads();
    if (tid == 0) {
        float S = 0.0f, Q = 0.0f;
        #pragma unroll
        for (int w = 0; w < NT / 32; w++) { S += s_s[w]; Q += s_q[w]; }
        g_part[row * CPR + c] = make_float2(S, Q);
    }
}

// Pass 2: fold partials -> mu, 1/sd; stream pooled -> duplicated normalized out.
__global__ __launch_bounds__(NT)
void pass2_kernel(float* __restrict__ out, int L) {
    const int halfL   = L >> 1;
    const int ngroups = halfL >> 2;
    const int gpc     = (ngroups + CPR - 1) / CPR;
    const int row     = blockIdx.x / CPR;
    const int c       = blockIdx.x % CPR;
    const int g_lo    = c * gpc;
    const int g_hi    = min(g_lo + gpc, ngroups);
    const int tid     = threadIdx.x;

    float S = 0.0f, Q = 0.0f;
    #pragma unroll
    for (int k = 0; k < CPR; k++) {
        float2 p = g_part[row * CPR + k];     // L2-hot, 128 B per row
        S += p.x; Q += p.y;
    }
    const float inv_n  = 1.0f / (float)halfL;
    const float mu     = S * inv_n;
    const float inv_sd = rsqrtf(fmaxf(Q * inv_n - mu * mu, 0.0f));

    const float* __restrict__ prow = g_pool + (size_t)row * (size_t)halfL;
    float*       __restrict__ orow = out + (size_t)row * (size_t)L;

    for (int g = g_lo + tid; g < g_hi; g += NT) {
        const int j0 = g << 2;
        float4 p = *reinterpret_cast<const float4*>(prow + j0);
        float v0 = (p.x - mu) * inv_sd, v1 = (p.y - mu) * inv_sd;
        float v2 = (p.z - mu) * inv_sd, v3 = (p.w - mu) * inv_sd;
        float4 w0 = {v0, v0, v1, v1}, w1 = {v2, v2, v3, v3};
        __stcs(reinterpret_cast<float4*>(orow + (j0 << 1)),     w0);
        __stcs(reinterpret_cast<float4*>(orow + (j0 << 1) + 4), w1);
    }
    if (c == CPR - 1) {
        for (int j = (ngroups << 2) + tid; j < halfL; j += NT) {
            float v = (prow[j] - mu) * inv_sd;
            orow[2 * j]     = v;
            orow[2 * j + 1] = v;
        }
    }
}

extern "C" void kernel_launch(void* const* d_in, const int* in_sizes, int n_in,
                              void* d_out, int out_size) {
    const float* x     = (const float*)d_in[0];
    const float* noise = (const float*)d_in[1];
    const int*   move  = (const int*)d_in[2];
    float*       out   = (float*)d_out;

    const int L     = in_sizes[1];          // 100000
    const int B     = in_sizes[0] / L;      // 512
    const int halfL = L / 2;

    npool_kernel<<<(halfL + 255) / 256, 256>>>(noise, halfL);
    pass1_kernel<<<B * CPR, NT>>>(x, move, L);
    pass2_kernel<<<B * CPR, NT>>>(out, L);
}

// round 12
// speedup vs baseline: 1.2627x; 1.1545x over previous
#include <cuda_runtime.h>
#include <cuda_fp16.h>
#include <math.h>

#define MAX_B    512
#define MAX_HALF 50048
#define CPR      16          // chunk CTAs per row
#define NT       256         // threads per CTA

// Row-invariant pooled noise: (noise[2j]+noise[2j+1])*STD/2 (STD=0.04)
__device__ float  g_npool[MAX_HALF];
// Pooled rows scratch in fp16 (51 MB) — written pass1, read pass2; fits L2.
__device__ __half g_pool[(size_t)MAX_B * MAX_HALF];
// Per-(row,chunk) partial moments {sum, sumsq}
__device__ float2 g_part[MAX_B * CPR];

__global__ void npool_kernel(const float* __restrict__ noise, int halfL) {
    int j = blockIdx.x * blockDim.x + threadIdx.x;
    if (j < halfL)
        g_npool[j] = (noise[2 * j] + noise[2 * j + 1]) * 0.02f;
}

// Pass 1: stream x (ldcs), pooled fp16 -> g_pool (default policy: L2-resident),
// partial (sum,sumsq) per chunk -> g_part. 8 pooled values per hot iteration.
__global__ __launch_bounds__(NT)
void pass1_kernel(const float* __restrict__ x,
                  const int*   __restrict__ move_p,
                  int L) {
    const int halfL   = L >> 1;
    const int ngroups = halfL >> 3;                 // groups of 8 pooled
    const int gpc     = (ngroups + CPR - 1) / CPR;
    const int row     = blockIdx.x / CPR;
    const int c       = blockIdx.x % CPR;
    const int gc_lo   = c * gpc;
    const int gc_hi   = min(gc_lo + gpc, ngroups);
    const int tid     = threadIdx.x;

    const float* __restrict__ xrow = x + (size_t)row * (size_t)L;
    __half*      __restrict__ prow = g_pool + (size_t)row * (size_t)halfL;

    int mv = __ldg(move_p);
    mv %= L; if (mv < 0) mv += L;

    // Fast-path interval in group-of-8 space: s0 = 16g - mv needs
    // s0 >= 0, s0+15 < L, and 16B alignment (mv % 4 == 0).
    int fl, fh;
    if ((mv & 3) == 0) {
        fl = (mv + 15) >> 4;           if (fl > ngroups) fl = ngroups;
        fh = (L + mv - 16) / 16 + 1;   if (fh > ngroups) fh = ngroups;
        if (fh < fl) fh = fl;
    } else { fl = 0; fh = 0; }

    int lo = max(gc_lo, fl); if (lo > gc_hi) lo = gc_hi;
    int hi = min(gc_hi, fh); if (hi < lo)    hi = lo;

    float sum = 0.0f, sumsq = 0.0f;

    // ---- scalar edge groups (wrap region) ----
    const int n_low = lo - gc_lo, n_high = gc_hi - hi;
    for (int e = tid; e < n_low + n_high; e += NT) {
        int g = (e < n_low) ? (gc_lo + e) : (hi + (e - n_low));
        int j0 = g << 3;
        #pragma unroll
        for (int k = 0; k < 8; k++) {
            int j = j0 + k;
            int s = 2 * j - mv;
            if (s < 0) s += L; else if (s >= L) s -= L;
            int s1 = s + 1; if (s1 >= L) s1 -= L;
            float p = (xrow[s] + xrow[s1]) * 0.5f + g_npool[j];
            prow[j] = __float2half_rn(p);
            sum += p; sumsq = fmaf(p, p, sumsq);
        }
    }
    // tail pooled indices (halfL % 8 != 0), owned by last chunk
    if (c == CPR - 1) {
        for (int j = (ngroups << 3) + tid; j < halfL; j += NT) {
            int s = 2 * j - mv;
            if (s < 0) s += L; else if (s >= L) s -= L;
            int s1 = s + 1; if (s1 >= L) s1 -= L;
            float p = (xrow[s] + xrow[s1]) * 0.5f + g_npool[j];
            prow[j] = __float2half_rn(p);
            sum += p; sumsq = fmaf(p, p, sumsq);
        }
    }

    // ---- hot loop: 4x LDG.128 (x) + 2x LDG.128 (npool) + 1x STG.128 (fp16) ----
    for (int g = lo + tid; g < hi; g += NT) {
        const int j0 = g << 3;
        const int s0 = (g << 4) - mv;
        float4 a = __ldcs(reinterpret_cast<const float4*>(xrow + s0));
        float4 b = __ldcs(reinterpret_cast<const float4*>(xrow + s0 + 4));
        float4 d = __ldcs(reinterpret_cast<const float4*>(xrow + s0 + 8));
        float4 e = __ldcs(reinterpret_cast<const float4*>(xrow + s0 + 12));
        float4 n0 = *reinterpret_cast<const float4*>(g_npool + j0);
        float4 n1 = *reinterpret_cast<const float4*>(g_npool + j0 + 4);

        float p0 = (a.x + a.y) * 0.5f + n0.x;
        float p1 = (a.z + a.w) * 0.5f + n0.y;
        float p2 = (b.x + b.y) * 0.5f + n0.z;
        float p3 = (b.z + b.w) * 0.5f + n0.w;
        float p4 = (d.x + d.y) * 0.5f + n1.x;
        float p5 = (d.z + d.w) * 0.5f + n1.y;
        float p6 = (e.x + e.y) * 0.5f + n1.z;
        float p7 = (e.z + e.w) * 0.5f + n1.w;

        __half2 h0 = __floats2half2_rn(p0, p1);
        __half2 h1 = __floats2half2_rn(p2, p3);
        __half2 h2 = __floats2half2_rn(p4, p5);
        __half2 h3 = __floats2half2_rn(p6, p7);
        uint4 packed;
        packed.x = *reinterpret_cast<unsigned int*>(&h0);
        packed.y = *reinterpret_cast<unsigned int*>(&h1);
        packed.z = *reinterpret_cast<unsigned int*>(&h2);
        packed.w = *reinterpret_cast<unsigned int*>(&h3);
        *reinterpret_cast<uint4*>(prow + j0) = packed;  // default policy -> L2

        sum  += ((p0 + p1) + (p2 + p3)) + ((p4 + p5) + (p6 + p7));
        sumsq = fmaf(p0, p0, sumsq); sumsq = fmaf(p1, p1, sumsq);
        sumsq = fmaf(p2, p2, sumsq); sumsq = fmaf(p3, p3, sumsq);
        sumsq = fmaf(p4, p4, sumsq); sumsq = fmaf(p5, p5, sumsq);
        sumsq = fmaf(p6, p6, sumsq); sumsq = fmaf(p7, p7, sumsq);
    }

    // ---- deterministic block reduction ----
    __shared__ float s_s[NT / 32], s_q[NT / 32];
    #pragma unroll
    for (int o = 16; o > 0; o >>= 1) {
        sum   += __shfl_down_sync(0xFFFFFFFFu, sum,   o);
        sumsq += __shfl_down_sync(0xFFFFFFFFu, sumsq, o);
    }
    if ((tid & 31) == 0) { s_s[tid >> 5] = sum; s_q[tid >> 5] = sumsq; }
    __syncthreads();
    if (tid == 0) {
        float S = 0.0f, Q = 0.0f;
        #pragma unroll
        for (int w = 0; w < NT / 32; w++) { S += s_s[w]; Q += s_q[w]; }
        g_part[row * CPR + c] = make_float2(S, Q);
    }
}

// Pass 2: fold partials -> mu, 1/sd; fp16 scratch (L2) -> duplicated fp32 out.
__global__ __launch_bounds__(NT)
void pass2_kernel(float* __restrict__ out, int L) {
    const int halfL   = L >> 1;
    const int ngroups = halfL >> 3;
    const int gpc     = (ngroups + CPR - 1) / CPR;
    const int row     = blockIdx.x / CPR;
    const int c       = blockIdx.x % CPR;
    const int g_lo    = c * gpc;
    const int g_hi    = min(g_lo + gpc, ngroups);
    const int tid     = threadIdx.x;

    float S = 0.0f, Q = 0.0f;
    #pragma unroll
    for (int k = 0; k < CPR; k++) {
        float2 p = g_part[row * CPR + k];       // 128 B per row, L2-hot
        S += p.x; Q += p.y;
    }
    const float inv_n  = 1.0f / (float)halfL;
    const float mu     = S * inv_n;
    const float inv_sd = rsqrtf(fmaxf(Q * inv_n - mu * mu, 0.0f));

    const __half* __restrict__ prow = g_pool + (size_t)row * (size_t)halfL;
    float*        __restrict__ orow = out + (size_t)row * (size_t)L;

    for (int g = g_lo + tid; g < g_hi; g += NT) {
        const int j0 = g << 3;
        uint4 raw = *reinterpret_cast<const uint4*>(prow + j0);   // 8 halves
        float2 f0 = __half22float2(*reinterpret_cast<__half2*>(&raw.x));
        float2 f1 = __half22float2(*reinterpret_cast<__half2*>(&raw.y));
        float2 f2 = __half22float2(*reinterpret_cast<__half2*>(&raw.z));
        float2 f3 = __half22float2(*reinterpret_cast<__half2*>(&raw.w));
        float v0 = (f0.x - mu) * inv_sd, v1 = (f0.y - mu) * inv_sd;
        float v2 = (f1.x - mu) * inv_sd, v3 = (f1.y - mu) * inv_sd;
        float v4 = (f2.x - mu) * inv_sd, v5 = (f2.y - mu) * inv_sd;
        float v6 = (f3.x - mu) * inv_sd, v7 = (f3.y - mu) * inv_sd;
        float4 w0 = {v0, v0, v1, v1}, w1 = {v2, v2, v3, v3};
        float4 w2 = {v4, v4, v5, v5}, w3 = {v6, v6, v7, v7};
        float* o = orow + (j0 << 1);
        __stcs(reinterpret_cast<float4*>(o),      w0);
        __stcs(reinterpret_cast<float4*>(o + 4),  w1);
        __stcs(reinterpret_cast<float4*>(o + 8),  w2);
        __stcs(reinterpret_cast<float4*>(o + 12), w3);
    }
    if (c == CPR - 1) {
        for (int j = (ngroups << 3) + tid; j < halfL; j += NT) {
            float v = (__half2float(prow[j]) - mu) * inv_sd;
            orow[2 * j]     = v;
            orow[2 * j + 1] = v;
        }
    }
}

extern "C" void kernel_launch(void* const* d_in, const int* in_sizes, int n_in,
                              void* d_out, int out_size) {
    const float* x     = (const float*)d_in[0];
    const float* noise = (const float*)d_in[1];
    const int*   move  = (const int*)d_in[2];
    float*       out   = (float*)d_out;

    const int L     = in_sizes[1];          // 100000
    const int B     = in_sizes[0] / L;      // 512
    const int halfL = L / 2;

    npool_kernel<<<(halfL + 255) / 256, 256>>>(noise, halfL);
    pass1_kernel<<<B * CPR, NT>>>(x, move, L);
    pass2_kernel<<<B * CPR, NT>>>(out, L);
}